// round 15
// baseline (speedup 1.0000x reference)
#include <cuda_runtime.h>
#include <stdint.h>

#define BATCH 16
#define SEQ   2048
#define DIM   64
#define BQ    64
#define BK    64
#define NCHUNK (SEQ / BK)
#define NT    256

// Double-buffered bf16 K/V chunk tiles; each buffer 32KB.
#define SO_KH 0
#define SO_KL 8192
#define SO_VH 16384
#define SO_VL 24576
#define BUFSZ 32768
// Q staging (prologue only) reuses buffer 0
#define SO_QH 0
#define SO_QL 8192
#define SMEM_TOTAL (2 * BUFSZ)
#define LDO   66          // epilogue O-exchange row stride (floats)

__device__ __forceinline__ uint32_t smem_u32(const void* p) {
    uint32_t a;
    asm("{ .reg .u64 t; cvta.to.shared.u64 t, %1; cvt.u32.u64 %0, t; }" : "=r"(a) : "l"(p));
    return a;
}
__device__ __forceinline__ uint32_t swz(uint32_t o) { return o ^ ((o >> 3) & 0x70); }
__device__ __forceinline__ uint32_t bf2(float lo, float hi) {   // pack {lo,hi} bf16x2
    uint32_t r; asm("cvt.rn.bf16x2.f32 %0, %1, %2;" : "=r"(r) : "f"(hi), "f"(lo)); return r;
}
__device__ __forceinline__ float bflo(uint32_t p) { return __uint_as_float(p << 16); }
__device__ __forceinline__ float bfhi(uint32_t p) { return __uint_as_float(p & 0xFFFF0000u); }
#define EX2F(d, a) asm("ex2.approx.f32 %0, %1;" : "=f"(d) : "f"(a))

#define LDSM4(r0, r1, r2, r3, a) \
    asm volatile("ldmatrix.sync.aligned.m8n8.x4.shared.b16 {%0,%1,%2,%3}, [%4];" \
                 : "=r"(r0), "=r"(r1), "=r"(r2), "=r"(r3) : "r"(a))
#define LDSM4T(r0, r1, r2, r3, a) \
    asm volatile("ldmatrix.sync.aligned.m8n8.x4.trans.shared.b16 {%0,%1,%2,%3}, [%4];" \
                 : "=r"(r0), "=r"(r1), "=r"(r2), "=r"(r3) : "r"(a))

__device__ __forceinline__ void mma_bf16(float* d, const uint32_t* a, uint32_t b0, uint32_t b1) {
    asm volatile("mma.sync.aligned.m16n8k16.row.col.f32.bf16.bf16.f32 "
                 "{%0,%1,%2,%3}, {%4,%5,%6,%7}, {%8,%9}, {%0,%1,%2,%3};"
                 : "+f"(d[0]), "+f"(d[1]), "+f"(d[2]), "+f"(d[3])
                 : "r"(a[0]), "r"(a[1]), "r"(a[2]), "r"(a[3]), "r"(b0), "r"(b1));
}

// split 16 fp32 (4 float4) into bf16 hi/lo, store as 2x 16B chunks per tile
__device__ __forceinline__ void split_store(char* base, int oh, int ol, uint32_t rel0,
                                            float4 f0, float4 f1, float4 f2, float4 f3) {
    uint32_t h0 = bf2(f0.x, f0.y), h1 = bf2(f0.z, f0.w);
    uint32_t h2 = bf2(f1.x, f1.y), h3 = bf2(f1.z, f1.w);
    uint32_t h4 = bf2(f2.x, f2.y), h5 = bf2(f2.z, f2.w);
    uint32_t h6 = bf2(f3.x, f3.y), h7 = bf2(f3.z, f3.w);
    uint32_t l0 = bf2(f0.x - bflo(h0), f0.y - bfhi(h0));
    uint32_t l1 = bf2(f0.z - bflo(h1), f0.w - bfhi(h1));
    uint32_t l2 = bf2(f1.x - bflo(h2), f1.y - bfhi(h2));
    uint32_t l3 = bf2(f1.z - bflo(h3), f1.w - bfhi(h3));
    uint32_t l4 = bf2(f2.x - bflo(h4), f2.y - bfhi(h4));
    uint32_t l5 = bf2(f2.z - bflo(h5), f2.w - bfhi(h5));
    uint32_t l6 = bf2(f3.x - bflo(h6), f3.y - bfhi(h6));
    uint32_t l7 = bf2(f3.z - bflo(h7), f3.w - bfhi(h7));
    *(uint4*)(base + oh + swz(rel0))      = make_uint4(h0, h1, h2, h3);
    *(uint4*)(base + oh + swz(rel0 + 16)) = make_uint4(h4, h5, h6, h7);
    *(uint4*)(base + ol + swz(rel0))      = make_uint4(l0, l1, l2, l3);
    *(uint4*)(base + ol + swz(rel0 + 16)) = make_uint4(l4, l5, l6, l7);
}

__global__ __launch_bounds__(NT, 1)
void attn_mma(const float* __restrict__ q,
              const float* __restrict__ k,
              const float* __restrict__ v,
              const int* __restrict__ mask,
              float* __restrict__ out) {
    extern __shared__ char smem[];
    const uint32_t sb = smem_u32(smem);
    const int t = threadIdx.x, lid = t & 31, wid = t >> 5;
    const int b = blockIdx.y, q0 = blockIdx.x * BQ;
    const int mg = wid >> 1;          // m-group: 16 query rows
    const int nh = wid & 1;           // key half: 32 keys of each chunk

    const float* qg = q + ((size_t)b * SEQ + q0) * DIM;
    const float* kg = k + (size_t)b * SEQ * DIM;
    const float* vg = v + (size_t)b * SEQ * DIM;
    const float QS = 0.125f * 1.4426950408889634f;   // (1/temp)*log2(e), folded into Q

    const int lr = t & 63, seg = t >> 6;              // K/V loader mapping
    const uint32_t kvrel = (uint32_t)lr * 128 + seg * 32;

    // ---- Issue chunk-0 K/V loads first (latency overlapped with Q staging) ----
    float4 pk[4], pv[4];
    {
        const float4* kp = (const float4*)(kg + (size_t)lr * DIM + seg * 16);
        const float4* vp = (const float4*)(vg + (size_t)lr * DIM + seg * 16);
#pragma unroll
        for (int j = 0; j < 4; j++) { pk[j] = kp[j]; pv[j] = vp[j]; }
    }

    // ---- Stage Q (scaled, hi/lo) into buf0: 4 threads/row x 16 dims each ----
    {
        int r = t >> 2, quar = t & 3;
        const float4* qp = (const float4*)(qg + (size_t)r * DIM + quar * 16);
        float4 f[4];
#pragma unroll
        for (int j = 0; j < 4; j++) {
            f[j] = qp[j];
            f[j].x *= QS; f[j].y *= QS; f[j].z *= QS; f[j].w *= QS;
        }
        split_store(smem, SO_QH, SO_QL, (uint32_t)r * 128 + quar * 32,
                    f[0], f[1], f[2], f[3]);
    }
    __syncthreads();

    uint32_t qh[4][4], ql[4][4];
    {
        const int qb = mg * 16;
        const int rowoff = ((lid >> 3) & 1) * 8 + (lid & 7);
        const int cpar = (lid >> 4) & 1;
#pragma unroll
        for (int kt = 0; kt < 4; kt++) {
            uint32_t rel = (uint32_t)(qb + rowoff) * 128 + (2 * kt + cpar) * 16;
            LDSM4(qh[kt][0], qh[kt][1], qh[kt][2], qh[kt][3], sb + SO_QH + swz(rel));
            LDSM4(ql[kt][0], ql[kt][1], ql[kt][2], ql[kt][3], sb + SO_QL + swz(rel));
        }
    }
    __syncthreads();

    // ---- Commit chunk 0 into buffer 0 ----
    split_store(smem, SO_KH, SO_KL, kvrel, pk[0], pk[1], pk[2], pk[3]);
    split_store(smem, SO_VH, SO_VL, kvrel, pv[0], pv[1], pv[2], pv[3]);
    __syncthreads();

    float O[8][4];
#pragma unroll
    for (int i = 0; i < 8; i++)
#pragma unroll
        for (int j = 0; j < 4; j++) O[i][j] = 0.f;
    float lr0 = 0.f, lr1 = 0.f;

    const int g = lid >> 2, tc2 = (lid & 3) * 2;
    const int* mrow0 = mask + ((size_t)b * SEQ + q0 + mg * 16 + g) * SEQ + nh * 32 + tc2;
    const int* mrow1 = mrow0 + 8 * SEQ;

    const int krowoff = ((lid >> 4) & 1) * 8 + (lid & 7);  // K B-frag lane map
    const int kpar    = (lid >> 3) & 1;
    const int vrowoff = ((lid >> 3) & 1) * 8 + (lid & 7);  // V B-frag lane map (trans)
    const int vpar    = (lid >> 4) & 1;

    for (int kc = 0; kc < NCHUNK; kc++) {
        const int k0 = kc * BK;
        const uint32_t bc = sb + (uint32_t)(kc & 1) * BUFSZ;   // current buffer (read)
        char* bn = smem + ((kc & 1) ^ 1) * BUFSZ;              // next buffer (write)

        // ---- Issue next chunk's K/V global loads (consumed at loop bottom) ----
        if (kc + 1 < NCHUNK) {
            const float4* kp = (const float4*)(kg + (size_t)(k0 + BK + lr) * DIM + seg * 16);
            const float4* vp = (const float4*)(vg + (size_t)(k0 + BK + lr) * DIM + seg * 16);
#pragma unroll
            for (int j = 0; j < 4; j++) { pk[j] = kp[j]; pv[j] = vp[j]; }
        }
        // ---- Issue this chunk's mask loads (consumed after QK) ----
        int2 ms0[4], ms1[4];
#pragma unroll
        for (int nt = 0; nt < 4; nt++) {
            ms0[nt] = *(const int2*)(mrow0 + k0 + nt * 8);
            ms1[nt] = *(const int2*)(mrow1 + k0 + nt * 8);
        }

        // ---- QK^T over this warp's 32-key half: sc[4 n-tiles][4] ----
        float sc[4][4];
#pragma unroll
        for (int i = 0; i < 4; i++)
#pragma unroll
            for (int j = 0; j < 4; j++) sc[i][j] = 0.f;

        uint32_t bf[8][4];   // all B-frags of one operand set in registers
        // phase A: Kh -> Qh*Kh + Ql*Kh
#pragma unroll
        for (int pp = 0; pp < 2; pp++)
#pragma unroll
            for (int kt = 0; kt < 4; kt++) {
                uint32_t rel = (uint32_t)(16 * (2 * nh + pp) + krowoff) * 128
                             + (2 * kt + kpar) * 16;
                LDSM4(bf[pp * 4 + kt][0], bf[pp * 4 + kt][1],
                      bf[pp * 4 + kt][2], bf[pp * 4 + kt][3], bc + SO_KH + swz(rel));
            }
#pragma unroll
        for (int pp = 0; pp < 2; pp++)
#pragma unroll
            for (int kt = 0; kt < 4; kt++) {
                const uint32_t* f = bf[pp * 4 + kt];
                mma_bf16(sc[2 * pp],     qh[kt], f[0], f[1]);
                mma_bf16(sc[2 * pp],     ql[kt], f[0], f[1]);
                mma_bf16(sc[2 * pp + 1], qh[kt], f[2], f[3]);
                mma_bf16(sc[2 * pp + 1], ql[kt], f[2], f[3]);
            }
        // phase B: Kl -> Qh*Kl
#pragma unroll
        for (int pp = 0; pp < 2; pp++)
#pragma unroll
            for (int kt = 0; kt < 4; kt++) {
                uint32_t rel = (uint32_t)(16 * (2 * nh + pp) + krowoff) * 128
                             + (2 * kt + kpar) * 16;
                LDSM4(bf[pp * 4 + kt][0], bf[pp * 4 + kt][1],
                      bf[pp * 4 + kt][2], bf[pp * 4 + kt][3], bc + SO_KL + swz(rel));
            }
#pragma unroll
        for (int pp = 0; pp < 2; pp++)
#pragma unroll
            for (int kt = 0; kt < 4; kt++) {
                const uint32_t* f = bf[pp * 4 + kt];
                mma_bf16(sc[2 * pp],     qh[kt], f[0], f[1]);
                mma_bf16(sc[2 * pp + 1], qh[kt], f[2], f[3]);
            }

        // ---- Softmax: mask-select + ex2 (s already in log2 units) ----
#pragma unroll
        for (int nt = 0; nt < 4; nt++) {
            // masked latent = 1e-9 -> p = exp(1e-9) ~= 1.0 (2^0)
            float f0 = ms0[nt].x ? 0.f : sc[nt][0];
            float f1 = ms0[nt].y ? 0.f : sc[nt][1];
            float f2 = ms1[nt].x ? 0.f : sc[nt][2];
            float f3 = ms1[nt].y ? 0.f : sc[nt][3];
            float p0, p1, p2, p3;
            EX2F(p0, f0); EX2F(p1, f1); EX2F(p2, f2); EX2F(p3, f3);
            sc[nt][0] = p0; sc[nt][1] = p1; sc[nt][2] = p2; sc[nt][3] = p3;
            lr0 += p0 + p1;
            lr1 += p2 + p3;
        }

        // ---- P -> A-frags (hi/lo) in registers (D-layout == A-layout) ----
        uint32_t aph[2][4], apl[2][4];
#pragma unroll
        for (int j = 0; j < 2; j++) {
            const float* ta = sc[2 * j];
            const float* tb = sc[2 * j + 1];
            uint32_t x;
            x = bf2(ta[0], ta[1]); aph[j][0] = x;
            apl[j][0] = bf2(ta[0] - bflo(x), ta[1] - bfhi(x));
            x = bf2(ta[2], ta[3]); aph[j][1] = x;
            apl[j][1] = bf2(ta[2] - bflo(x), ta[3] - bfhi(x));
            x = bf2(tb[0], tb[1]); aph[j][2] = x;
            apl[j][2] = bf2(tb[0] - bflo(x), tb[1] - bfhi(x));
            x = bf2(tb[2], tb[3]); aph[j][3] = x;
            apl[j][3] = bf2(tb[2] - bflo(x), tb[3] - bfhi(x));
        }

        // ---- PV over this warp's 32 keys: O += P * V ----
        // phase A: Vh -> Ph*Vh + Pl*Vh
#pragma unroll
        for (int j = 0; j < 2; j++)
#pragma unroll
            for (int n2 = 0; n2 < 4; n2++) {
                uint32_t rel = (uint32_t)(nh * 32 + 16 * j + vrowoff) * 128
                             + (2 * n2 + vpar) * 16;
                LDSM4T(bf[j * 4 + n2][0], bf[j * 4 + n2][1],
                       bf[j * 4 + n2][2], bf[j * 4 + n2][3], bc + SO_VH + swz(rel));
            }
#pragma unroll
        for (int j = 0; j < 2; j++)
#pragma unroll
            for (int n2 = 0; n2 < 4; n2++) {
                const uint32_t* f = bf[j * 4 + n2];
                mma_bf16(O[2 * n2],     aph[j], f[0], f[1]);
                mma_bf16(O[2 * n2],     apl[j], f[0], f[1]);
                mma_bf16(O[2 * n2 + 1], aph[j], f[2], f[3]);
                mma_bf16(O[2 * n2 + 1], apl[j], f[2], f[3]);
            }
        // phase B: Vl -> Ph*Vl
#pragma unroll
        for (int j = 0; j < 2; j++)
#pragma unroll
            for (int n2 = 0; n2 < 4; n2++) {
                uint32_t rel = (uint32_t)(nh * 32 + 16 * j + vrowoff) * 128
                             + (2 * n2 + vpar) * 16;
                LDSM4T(bf[j * 4 + n2][0], bf[j * 4 + n2][1],
                       bf[j * 4 + n2][2], bf[j * 4 + n2][3], bc + SO_VL + swz(rel));
            }
#pragma unroll
        for (int j = 0; j < 2; j++)
#pragma unroll
            for (int n2 = 0; n2 < 4; n2++) {
                const uint32_t* f = bf[j * 4 + n2];
                mma_bf16(O[2 * n2],     aph[j], f[0], f[1]);
                mma_bf16(O[2 * n2 + 1], aph[j], f[2], f[3]);
            }

        // ---- Commit prefetched chunk into the other buffer ----
        if (kc + 1 < NCHUNK) {
            split_store(bn, SO_KH, SO_KL, kvrel, pk[0], pk[1], pk[2], pk[3]);
            split_store(bn, SO_VH, SO_VL, kvrel, pv[0], pv[1], pv[2], pv[3]);
        }
        __syncthreads();
    }

    // ---- Epilogue: combine key-half partials (O and l) across warp pairs ----
    lr0 += __shfl_xor_sync(0xffffffffu, lr0, 1);
    lr0 += __shfl_xor_sync(0xffffffffu, lr0, 2);
    lr1 += __shfl_xor_sync(0xffffffffu, lr1, 1);
    lr1 += __shfl_xor_sync(0xffffffffu, lr1, 2);

    float* sO = (float*)smem;                    // [64][LDO]
    float* sL = (float*)(smem + 64 * LDO * 4);   // [64]
    __syncthreads();
    if (nh == 1) {
        const int r0i = mg * 16 + g, r1i = r0i + 8;
#pragma unroll
        for (int ti = 0; ti < 8; ti++) {
            *(float2*)(sO + r0i * LDO + ti * 8 + tc2) = make_float2(O[ti][0], O[ti][1]);
            *(float2*)(sO + r1i * LDO + ti * 8 + tc2) = make_float2(O[ti][2], O[ti][3]);
        }
        if ((lid & 3) == 0) { sL[r0i] = lr0; sL[r1i] = lr1; }
    }
    __syncthreads();
    if (nh == 0) {
        const int r0i = mg * 16 + g, r1i = r0i + 8;
        float lt0 = lr0 + sL[r0i];
        float lt1 = lr1 + sL[r1i];
        const float inv0 = 1.f / lt0, inv1 = 1.f / lt1;
        float* o0 = out + ((size_t)b * SEQ + q0 + r0i) * DIM;
        float* o1 = out + ((size_t)b * SEQ + q0 + r1i) * DIM;
#pragma unroll
        for (int ti = 0; ti < 8; ti++) {
            float2 e0 = *(float2*)(sO + r0i * LDO + ti * 8 + tc2);
            float2 e1 = *(float2*)(sO + r1i * LDO + ti * 8 + tc2);
            *(float2*)(o0 + ti * 8 + tc2) =
                make_float2((O[ti][0] + e0.x) * inv0, (O[ti][1] + e0.y) * inv0);
            *(float2*)(o1 + ti * 8 + tc2) =
                make_float2((O[ti][2] + e1.x) * inv1, (O[ti][3] + e1.y) * inv1);
        }
    }
}

extern "C" void kernel_launch(void* const* d_in, const int* in_sizes, int n_in,
                              void* d_out, int out_size) {
    const float* q = (const float*)d_in[0];
    const float* k = (const float*)d_in[1];
    const float* v = (const float*)d_in[2];
    const int*   mask = (const int*)d_in[3];
    float* out = (float*)d_out;

    cudaFuncSetAttribute(attn_mma, cudaFuncAttributeMaxDynamicSharedMemorySize, SMEM_TOTAL);
    dim3 grid(SEQ / BQ, BATCH);
    attn_mma<<<grid, NT, SMEM_TOTAL>>>(q, k, v, mask, out);
}

// round 17
// speedup vs baseline: 1.8543x; 1.8543x over previous
#include <cuda_runtime.h>
#include <stdint.h>

#define BATCH 16
#define SEQ   2048
#define DIM   64
#define BQ    128
#define BK    64
#define NCHUNK (SEQ / BK)
#define NT    256

// Double-buffered bf16 K/V chunk tiles; each buffer 32KB.
#define SO_KH 0
#define SO_KL 8192
#define SO_VH 16384
#define SO_VL 24576
#define BUFSZ 32768
// Q staging (prologue only) reuses buffer 0
#define SO_QH 0
#define SO_QL 16384
#define SMEM_TOTAL (2 * BUFSZ)

__device__ __forceinline__ uint32_t smem_u32(const void* p) {
    uint32_t a;
    asm("{ .reg .u64 t; cvta.to.shared.u64 t, %1; cvt.u32.u64 %0, t; }" : "=r"(a) : "l"(p));
    return a;
}
__device__ __forceinline__ uint32_t swz(uint32_t o) { return o ^ ((o >> 3) & 0x70); }
__device__ __forceinline__ uint32_t bf2(float lo, float hi) {   // pack {lo,hi} bf16x2
    uint32_t r; asm("cvt.rn.bf16x2.f32 %0, %1, %2;" : "=r"(r) : "f"(hi), "f"(lo)); return r;
}
__device__ __forceinline__ float bflo(uint32_t p) { return __uint_as_float(p << 16); }
__device__ __forceinline__ float bfhi(uint32_t p) { return __uint_as_float(p & 0xFFFF0000u); }
#define EX2F(d, a) asm("ex2.approx.f32 %0, %1;" : "=f"(d) : "f"(a))

#define LDSM4(r0, r1, r2, r3, a) \
    asm volatile("ldmatrix.sync.aligned.m8n8.x4.shared.b16 {%0,%1,%2,%3}, [%4];" \
                 : "=r"(r0), "=r"(r1), "=r"(r2), "=r"(r3) : "r"(a))
#define LDSM4T(r0, r1, r2, r3, a) \
    asm volatile("ldmatrix.sync.aligned.m8n8.x4.trans.shared.b16 {%0,%1,%2,%3}, [%4];" \
                 : "=r"(r0), "=r"(r1), "=r"(r2), "=r"(r3) : "r"(a))

__device__ __forceinline__ void mma_bf16(float* d, const uint32_t* a, uint32_t b0, uint32_t b1) {
    asm volatile("mma.sync.aligned.m16n8k16.row.col.f32.bf16.bf16.f32 "
                 "{%0,%1,%2,%3}, {%4,%5,%6,%7}, {%8,%9}, {%0,%1,%2,%3};"
                 : "+f"(d[0]), "+f"(d[1]), "+f"(d[2]), "+f"(d[3])
                 : "r"(a[0]), "r"(a[1]), "r"(a[2]), "r"(a[3]), "r"(b0), "r"(b1));
}

// split 16 fp32 (4 float4) into bf16 hi/lo, store as 2x 16B chunks per tile
// (used for Q staging in the prologue)
__device__ __forceinline__ void split_store(char* base, int oh, int ol, uint32_t rel0,
                                            float4 f0, float4 f1, float4 f2, float4 f3) {
    uint32_t h0 = bf2(f0.x, f0.y), h1 = bf2(f0.z, f0.w);
    uint32_t h2 = bf2(f1.x, f1.y), h3 = bf2(f1.z, f1.w);
    uint32_t h4 = bf2(f2.x, f2.y), h5 = bf2(f2.z, f2.w);
    uint32_t h6 = bf2(f3.x, f3.y), h7 = bf2(f3.z, f3.w);
    uint32_t l0 = bf2(f0.x - bflo(h0), f0.y - bfhi(h0));
    uint32_t l1 = bf2(f0.z - bflo(h1), f0.w - bfhi(h1));
    uint32_t l2 = bf2(f1.x - bflo(h2), f1.y - bfhi(h2));
    uint32_t l3 = bf2(f1.z - bflo(h3), f1.w - bfhi(h3));
    uint32_t l4 = bf2(f2.x - bflo(h4), f2.y - bfhi(h4));
    uint32_t l5 = bf2(f2.z - bflo(h5), f2.w - bfhi(h5));
    uint32_t l6 = bf2(f3.x - bflo(h6), f3.y - bfhi(h6));
    uint32_t l7 = bf2(f3.z - bflo(h7), f3.w - bfhi(h7));
    *(uint4*)(base + oh + swz(rel0))      = make_uint4(h0, h1, h2, h3);
    *(uint4*)(base + oh + swz(rel0 + 16)) = make_uint4(h4, h5, h6, h7);
    *(uint4*)(base + ol + swz(rel0))      = make_uint4(l0, l1, l2, l3);
    *(uint4*)(base + ol + swz(rel0 + 16)) = make_uint4(l4, l5, l6, l7);
}

// split one float4 (4 dims) into bf16 hi/lo, store 8B each (K/V commit path)
__device__ __forceinline__ void split_store4(char* base, int oh, int ol, uint32_t rel,
                                             float4 f) {
    uint32_t h0 = bf2(f.x, f.y), h1 = bf2(f.z, f.w);
    uint32_t l0 = bf2(f.x - bflo(h0), f.y - bfhi(h0));
    uint32_t l1 = bf2(f.z - bflo(h1), f.w - bfhi(h1));
    *(uint2*)(base + oh + swz(rel)) = make_uint2(h0, h1);
    *(uint2*)(base + ol + swz(rel)) = make_uint2(l0, l1);
}

__global__ __launch_bounds__(NT, 1)
void attn_mma(const float* __restrict__ q,
              const float* __restrict__ k,
              const float* __restrict__ v,
              const int* __restrict__ mask,
              float* __restrict__ out) {
    extern __shared__ char smem[];
    const uint32_t sb = smem_u32(smem);
    const int t = threadIdx.x, lid = t & 31, wid = t >> 5;
    const int b = blockIdx.y, q0 = blockIdx.x * BQ;

    const float* qg = q + ((size_t)b * SEQ + q0) * DIM;
    const float* kg = k + (size_t)b * SEQ * DIM;
    const float* vg = v + (size_t)b * SEQ * DIM;
    const float QS = 0.125f * 1.4426950408889634f;   // (1/temp)*log2(e), folded into Q

    // Coalesced K/V loader: chunk is a contiguous 16KB block; thread t reads
    // bytes [t*16 + j*4096]. float4 index t + j*256 -> row=(t>>4)+j*16, dims=(t&15)*4.
    const uint32_t kvrel = ((uint32_t)(t >> 4)) * 128 + (t & 15) * 8;

    // ---- Issue chunk-0 K/V loads first (latency overlapped with Q staging) ----
    float4 pk[4], pv[4];
    {
        const float4* kc4 = (const float4*)kg;
        const float4* vc4 = (const float4*)vg;
#pragma unroll
        for (int j = 0; j < 4; j++) { pk[j] = kc4[t + j * 256]; pv[j] = vc4[t + j * 256]; }
    }

    // ---- Stage Q (scaled, hi/lo) into buf0: 2 threads/row x 32 dims each ----
    {
        int r = t >> 1, half = t & 1;
        const float4* qp = (const float4*)(qg + (size_t)r * DIM + half * 32);
        float4 f[8];
#pragma unroll
        for (int j = 0; j < 8; j++) {
            f[j] = qp[j];
            f[j].x *= QS; f[j].y *= QS; f[j].z *= QS; f[j].w *= QS;
        }
        uint32_t rel0 = (uint32_t)r * 128 + half * 64;
        split_store(smem, SO_QH, SO_QL, rel0,      f[0], f[1], f[2], f[3]);
        split_store(smem, SO_QH, SO_QL, rel0 + 32, f[4], f[5], f[6], f[7]);
    }
    __syncthreads();

    uint32_t qh[4][4], ql[4][4];
    {
        const int qb = wid * 16;
        const int rowoff = ((lid >> 3) & 1) * 8 + (lid & 7);
        const int cpar = (lid >> 4) & 1;
#pragma unroll
        for (int kt = 0; kt < 4; kt++) {
            uint32_t rel = (uint32_t)(qb + rowoff) * 128 + (2 * kt + cpar) * 16;
            LDSM4(qh[kt][0], qh[kt][1], qh[kt][2], qh[kt][3], sb + SO_QH + swz(rel));
            LDSM4(ql[kt][0], ql[kt][1], ql[kt][2], ql[kt][3], sb + SO_QL + swz(rel));
        }
    }
    __syncthreads();

    // ---- Commit chunk 0 into buffer 0 ----
#pragma unroll
    for (int j = 0; j < 4; j++) {
        uint32_t rel = kvrel + (uint32_t)j * 16 * 128;
        split_store4(smem, SO_KH, SO_KL, rel, pk[j]);
        split_store4(smem, SO_VH, SO_VL, rel, pv[j]);
    }
    __syncthreads();

    float O[8][4];
#pragma unroll
    for (int i = 0; i < 8; i++)
#pragma unroll
        for (int j = 0; j < 4; j++) O[i][j] = 0.f;
    float lr0 = 0.f, lr1 = 0.f;

    const int g = lid >> 2, tc2 = (lid & 3) * 2;
    const int* mrow0 = mask + ((size_t)b * SEQ + q0 + wid * 16 + g) * SEQ;
    const int* mrow1 = mrow0 + 8 * SEQ;

    const int krowoff = ((lid >> 4) & 1) * 8 + (lid & 7);  // K B-frag lane map
    const int kpar    = (lid >> 3) & 1;
    const int vrowoff = ((lid >> 3) & 1) * 8 + (lid & 7);  // V B-frag lane map (trans)
    const int vpar    = (lid >> 4) & 1;

    for (int kc = 0; kc < NCHUNK; kc++) {
        const int k0 = kc * BK;
        const uint32_t bc = sb + (uint32_t)(kc & 1) * BUFSZ;   // current buffer (read)
        char* bn = smem + ((kc & 1) ^ 1) * BUFSZ;              // next buffer (write)

        // ---- Issue next chunk's K/V global loads (consumed at loop bottom) ----
        if (kc + 1 < NCHUNK) {
            const float4* kc4 = (const float4*)(kg + (size_t)(k0 + BK) * DIM);
            const float4* vc4 = (const float4*)(vg + (size_t)(k0 + BK) * DIM);
#pragma unroll
            for (int j = 0; j < 4; j++) { pk[j] = kc4[t + j * 256]; pv[j] = vc4[t + j * 256]; }
        }
        // ---- Issue this chunk's mask loads (consumed after QK) ----
        int2 ms0[8], ms1[8];
#pragma unroll
        for (int ti = 0; ti < 8; ti++) {
            ms0[ti] = *(const int2*)(mrow0 + k0 + ti * 8 + tc2);
            ms1[ti] = *(const int2*)(mrow1 + k0 + ti * 8 + tc2);
        }

        // ---- QK^T: sc[8 n-tiles][4], 3 hi/lo combos ----
        float sc[8][4];
#pragma unroll
        for (int i = 0; i < 8; i++)
#pragma unroll
            for (int j = 0; j < 4; j++) sc[i][j] = 0.f;
#pragma unroll
        for (int kt = 0; kt < 4; kt++) {
#pragma unroll
            for (int p = 0; p < 4; p++) {
                uint32_t rel = (uint32_t)(16 * p + krowoff) * 128 + (2 * kt + kpar) * 16;
                uint32_t h0, h1, h2, h3, e0, e1, e2, e3;
                LDSM4(h0, h1, h2, h3, bc + SO_KH + swz(rel));
                LDSM4(e0, e1, e2, e3, bc + SO_KL + swz(rel));
                mma_bf16(sc[2 * p],     qh[kt], h0, h1);
                mma_bf16(sc[2 * p],     qh[kt], e0, e1);
                mma_bf16(sc[2 * p],     ql[kt], h0, h1);
                mma_bf16(sc[2 * p + 1], qh[kt], h2, h3);
                mma_bf16(sc[2 * p + 1], qh[kt], e2, e3);
                mma_bf16(sc[2 * p + 1], ql[kt], h2, h3);
            }
        }

        // ---- Softmax: mask-select + ex2 (s already in log2 units) ----
#pragma unroll
        for (int ti = 0; ti < 8; ti++) {
            // masked latent = 1e-9 -> p = exp(1e-9) ~= 1.0 (2^0)
            float f0 = ms0[ti].x ? 0.f : sc[ti][0];
            float f1 = ms0[ti].y ? 0.f : sc[ti][1];
            float f2 = ms1[ti].x ? 0.f : sc[ti][2];
            float f3 = ms1[ti].y ? 0.f : sc[ti][3];
            float p0, p1, p2, p3;
            EX2F(p0, f0); EX2F(p1, f1); EX2F(p2, f2); EX2F(p3, f3);
            sc[ti][0] = p0; sc[ti][1] = p1; sc[ti][2] = p2; sc[ti][3] = p3;
            lr0 += p0 + p1;
            lr1 += p2 + p3;
        }

        // ---- P -> A-frags (hi/lo) in registers (D-layout == A-layout) ----
        uint32_t aph[4][4], apl[4][4];
#pragma unroll
        for (int j = 0; j < 4; j++) {
            const float* ta = sc[2 * j];
            const float* tb = sc[2 * j + 1];
            uint32_t x;
            x = bf2(ta[0], ta[1]); aph[j][0] = x;
            apl[j][0] = bf2(ta[0] - bflo(x), ta[1] - bfhi(x));
            x = bf2(ta[2], ta[3]); aph[j][1] = x;
            apl[j][1] = bf2(ta[2] - bflo(x), ta[3] - bfhi(x));
            x = bf2(tb[0], tb[1]); aph[j][2] = x;
            apl[j][2] = bf2(tb[0] - bflo(x), tb[1] - bfhi(x));
            x = bf2(tb[2], tb[3]); aph[j][3] = x;
            apl[j][3] = bf2(tb[2] - bflo(x), tb[3] - bfhi(x));
        }

        // ---- PV: O += P * V, 3 combos ----
#pragma unroll
        for (int j = 0; j < 4; j++) {
#pragma unroll
            for (int n2 = 0; n2 < 4; n2++) {
                uint32_t rel = (uint32_t)(16 * j + vrowoff) * 128 + (2 * n2 + vpar) * 16;
                uint32_t h0, h1, h2, h3, e0, e1, e2, e3;
                LDSM4T(h0, h1, h2, h3, bc + SO_VH + swz(rel));
                LDSM4T(e0, e1, e2, e3, bc + SO_VL + swz(rel));
                mma_bf16(O[2 * n2],     aph[j], h0, h1);
                mma_bf16(O[2 * n2],     aph[j], e0, e1);
                mma_bf16(O[2 * n2],     apl[j], h0, h1);
                mma_bf16(O[2 * n2 + 1], aph[j], h2, h3);
                mma_bf16(O[2 * n2 + 1], aph[j], e2, e3);
                mma_bf16(O[2 * n2 + 1], apl[j], h2, h3);
            }
        }

        // ---- Commit prefetched chunk into the other buffer ----
        if (kc + 1 < NCHUNK) {
#pragma unroll
            for (int j = 0; j < 4; j++) {
                uint32_t rel = kvrel + (uint32_t)j * 16 * 128;
                split_store4(bn, SO_KH, SO_KL, rel, pk[j]);
                split_store4(bn, SO_VH, SO_VL, rel, pv[j]);
            }
        }
        __syncthreads();
    }

    // ---- Epilogue: reduce l over 4-lane row groups, normalize, store ----
    lr0 += __shfl_xor_sync(0xffffffffu, lr0, 1);
    lr0 += __shfl_xor_sync(0xffffffffu, lr0, 2);
    lr1 += __shfl_xor_sync(0xffffffffu, lr1, 1);
    lr1 += __shfl_xor_sync(0xffffffffu, lr1, 2);
    const float inv0 = 1.f / lr0, inv1 = 1.f / lr1;
    float* o0 = out + ((size_t)b * SEQ + q0 + wid * 16 + g) * DIM;
    float* o1 = o0 + 8 * DIM;
#pragma unroll
    for (int ti = 0; ti < 8; ti++) {
        int d = ti * 8 + tc2;
        *(float2*)(o0 + d) = make_float2(O[ti][0] * inv0, O[ti][1] * inv0);
        *(float2*)(o1 + d) = make_float2(O[ti][2] * inv1, O[ti][3] * inv1);
    }
}

extern "C" void kernel_launch(void* const* d_in, const int* in_sizes, int n_in,
                              void* d_out, int out_size) {
    const float* q = (const float*)d_in[0];
    const float* k = (const float*)d_in[1];
    const float* v = (const float*)d_in[2];
    const int*   mask = (const int*)d_in[3];
    float* out = (float*)d_out;

    cudaFuncSetAttribute(attn_mma, cudaFuncAttributeMaxDynamicSharedMemorySize, SMEM_TOTAL);
    dim3 grid(SEQ / BQ, BATCH);
    attn_mma<<<grid, NT, SMEM_TOTAL>>>(q, k, v, mask, out);
}